// round 4
// baseline (speedup 1.0000x reference)
#include <cuda_runtime.h>
#include <math.h>

#define BB   4
#define NY   16384
#define NX   4096
#define CY   128
#define CX   256
#define DIM  384
#define C1   512
#define C2   256
#define C3   128
#define NTOT (BB*NY)   // 65536

// ---------------- scratch (static device allocations) ----------------
__device__ float4 g_xpack[BB*NX];
__device__ int    g_nbi[NTOT*3];
__device__ float  g_nbw[NTOT*3];
__device__ float  g_F0[(size_t)NTOT*DIM];
__device__ float  g_Z1[(size_t)NTOT*C1];
__device__ float  g_Z2[(size_t)NTOT*C2];
__device__ float  g_Z3[(size_t)NTOT*C3];
__device__ double g_stats1[2*C1];
__device__ double g_stats2[2*C2];
__device__ double g_stats3[2*C3];
__device__ float  g_ab1[2*C1];
__device__ float  g_ab2[2*C2];
__device__ float  g_ab3[2*C3];

// ---------------- pack x points + zero stats ----------------
__global__ void k_pack(const float* __restrict__ xp) {
    int i = blockIdx.x * 256 + threadIdx.x;
    if (i < BB*NX) {
        float x = xp[i*3+0], y = xp[i*3+1], z = xp[i*3+2];
        float sx = __fadd_rn(__fadd_rn(__fmul_rn(x,x), __fmul_rn(y,y)), __fmul_rn(z,z));
        g_xpack[i] = make_float4(x, y, z, sx);
    }
    if (i < 2*C1) g_stats1[i] = 0.0;
    else if (i < 2*C1 + 2*C2) g_stats2[i - 2*C1] = 0.0;
    else if (i < 2*C1 + 2*C2 + 2*C3) g_stats3[i - 2*C1 - 2*C2] = 0.0;
}

// ---------------- 3-NN search (exact reference arithmetic order) ----------------
__global__ void k_knn(const float* __restrict__ yp) {
    __shared__ float4 sx[2048];
    int b = blockIdx.y;
    int n = b * NY + blockIdx.x * blockDim.x + threadIdx.x;
    float yx = yp[n*3+0], yy = yp[n*3+1], yz = yp[n*3+2];
    float sy = __fadd_rn(__fadd_rn(__fmul_rn(yx,yx), __fmul_rn(yy,yy)), __fmul_rn(yz,yz));
    float k0 = 1e30f, k1 = 1e30f, k2 = 1e30f;
    int   i0 = 0, i1 = 0, i2 = 0;

    for (int base = 0; base < NX; base += 2048) {
        __syncthreads();
        for (int i = threadIdx.x; i < 2048; i += blockDim.x)
            sx[i] = g_xpack[b*NX + base + i];
        __syncthreads();
        #pragma unroll 4
        for (int j = 0; j < 2048; j++) {
            float4 p = sx[j];
            float dot = __fmaf_rn(yz, p.z, __fmaf_rn(yy, p.y, __fmul_rn(yx, p.x)));
            float d = __fadd_rn(__fadd_rn(sy, p.w), -__fmul_rn(2.0f, dot));
            if (d < k2) {
                int jj = base + j;
                if (d < k1) {
                    k2 = k1; i2 = i1;
                    if (d < k0) { k1 = k0; i1 = i0; k0 = d; i0 = jj; }
                    else        { k1 = d; i1 = jj; }
                } else { k2 = d; i2 = jj; }
            }
        }
    }
    float w0 = __fdiv_rn(1.0f, __fadd_rn(k0, 1e-8f));
    float w1 = __fdiv_rn(1.0f, __fadd_rn(k1, 1e-8f));
    float w2 = __fdiv_rn(1.0f, __fadd_rn(k2, 1e-8f));
    float sw = __fadd_rn(__fadd_rn(w0, w1), w2);
    g_nbi[n*3+0] = i0; g_nbi[n*3+1] = i1; g_nbi[n*3+2] = i2;
    g_nbw[n*3+0] = __fdiv_rn(w0, sw);
    g_nbw[n*3+1] = __fdiv_rn(w1, sw);
    g_nbw[n*3+2] = __fdiv_rn(w2, sw);
}

// ---------------- gather + interpolate + concat -> F0 [N,384] ----------------
__global__ void k_gather(const float* __restrict__ yf, const float* __restrict__ xf) {
    int n = blockIdx.x;
    int t = threadIdx.x;
    int b = n >> 14;
    float* o = g_F0 + (size_t)n * DIM;
    o[t] = yf[(size_t)n * CY + t];
    int i0 = g_nbi[n*3+0], i1 = g_nbi[n*3+1], i2 = g_nbi[n*3+2];
    float w0 = g_nbw[n*3+0], w1 = g_nbw[n*3+1], w2 = g_nbw[n*3+2];
    const float* r0 = xf + ((size_t)(b*NX + i0)) * CX;
    const float* r1 = xf + ((size_t)(b*NX + i1)) * CX;
    const float* r2 = xf + ((size_t)(b*NX + i2)) * CX;
    o[CY + t] = __fadd_rn(__fadd_rn(__fmul_rn(r0[t], w0), __fmul_rn(r1[t], w1)),
                          __fmul_rn(r2[t], w2));
    o[CY + 128 + t] = __fadd_rn(__fadd_rn(__fmul_rn(r0[128+t], w0), __fmul_rn(r1[128+t], w1)),
                                __fmul_rn(r2[128+t], w2));
}

// ---------------- GEMM via packed fp32 (FFMA2): Z = act(A)·W^T + bias; + BN stats ----------------
template<int Kd, int Cout, bool ACT>
__global__ void __launch_bounds__(256)
k_gemm(const float* __restrict__ A, const float* __restrict__ W,
       const float* __restrict__ bias, const float* __restrict__ ab,
       float* __restrict__ Z, double* __restrict__ stats)
{
    const int S = 132;                 // smem row stride (floats), 16B-aligned
    __shared__ float As[16*S];
    __shared__ float Ws[16*S];
    __shared__ float sSum[128], sSq[128];

    int tid = threadIdx.x;
    int tx = tid & 15, ty = tid >> 4;
    int n0 = blockIdx.x * 128;
    int c0 = blockIdx.y * 128;
    if (tid < 128) { sSum[tid] = 0.f; sSq[tid] = 0.f; }

    // packed f32x2 accumulators: acc[i][jp] holds columns (2jp, 2jp+1) of row i
    unsigned long long acc[8][4];
    #pragma unroll
    for (int i = 0; i < 8; i++)
        #pragma unroll
        for (int j = 0; j < 4; j++) acc[i][j] = 0ull;

    int lr  = tid >> 1;          // tile row 0..127
    int kb  = (tid & 1) * 8;     // k offset within tile: 0 or 8

    for (int kt = 0; kt < Kd; kt += 16) {
        __syncthreads();
        {   // A tile (with fused BN+ReLU of previous layer)
            const float* src = A + (size_t)(n0 + lr) * Kd + kt + kb;
            float4 v0 = *(const float4*)(src);
            float4 v1 = *(const float4*)(src + 4);
            if (ACT) {
                float4 a0 = *(const float4*)(ab + kt + kb);
                float4 a1 = *(const float4*)(ab + kt + kb + 4);
                float4 s0 = *(const float4*)(ab + Kd + kt + kb);
                float4 s1 = *(const float4*)(ab + Kd + kt + kb + 4);
                v0.x = fmaxf(fmaf(a0.x, v0.x, s0.x), 0.f);
                v0.y = fmaxf(fmaf(a0.y, v0.y, s0.y), 0.f);
                v0.z = fmaxf(fmaf(a0.z, v0.z, s0.z), 0.f);
                v0.w = fmaxf(fmaf(a0.w, v0.w, s0.w), 0.f);
                v1.x = fmaxf(fmaf(a1.x, v1.x, s1.x), 0.f);
                v1.y = fmaxf(fmaf(a1.y, v1.y, s1.y), 0.f);
                v1.z = fmaxf(fmaf(a1.z, v1.z, s1.z), 0.f);
                v1.w = fmaxf(fmaf(a1.w, v1.w, s1.w), 0.f);
            }
            As[(kb+0)*S + lr] = v0.x; As[(kb+1)*S + lr] = v0.y;
            As[(kb+2)*S + lr] = v0.z; As[(kb+3)*S + lr] = v0.w;
            As[(kb+4)*S + lr] = v1.x; As[(kb+5)*S + lr] = v1.y;
            As[(kb+6)*S + lr] = v1.z; As[(kb+7)*S + lr] = v1.w;
        }
        {   // W tile
            const float* src = W + (size_t)(c0 + lr) * Kd + kt + kb;
            float4 v0 = *(const float4*)(src);
            float4 v1 = *(const float4*)(src + 4);
            Ws[(kb+0)*S + lr] = v0.x; Ws[(kb+1)*S + lr] = v0.y;
            Ws[(kb+2)*S + lr] = v0.z; Ws[(kb+3)*S + lr] = v0.w;
            Ws[(kb+4)*S + lr] = v1.x; Ws[(kb+5)*S + lr] = v1.y;
            Ws[(kb+6)*S + lr] = v1.z; Ws[(kb+7)*S + lr] = v1.w;
        }
        __syncthreads();
        #pragma unroll
        for (int kk = 0; kk < 16; kk++) {
            float a[8], w[8];
            *(float4*)&a[0] = *(const float4*)&As[kk*S + ty*8];
            *(float4*)&a[4] = *(const float4*)&As[kk*S + ty*8 + 4];
            *(float4*)&w[0] = *(const float4*)&Ws[kk*S + tx*8];
            *(float4*)&w[4] = *(const float4*)&Ws[kk*S + tx*8 + 4];
            unsigned long long wp[4], ap[8];
            #pragma unroll
            for (int j = 0; j < 4; j++)
                asm("mov.b64 %0, {%1, %2};" : "=l"(wp[j]) : "f"(w[2*j]), "f"(w[2*j+1]));
            #pragma unroll
            for (int i = 0; i < 8; i++)
                asm("mov.b64 %0, {%1, %1};" : "=l"(ap[i]) : "f"(a[i]));
            #pragma unroll
            for (int i = 0; i < 8; i++)
                #pragma unroll
                for (int j = 0; j < 4; j++)
                    asm("fma.rn.f32x2 %0, %1, %2, %3;"
                        : "=l"(acc[i][j]) : "l"(ap[i]), "l"(wp[j]), "l"(acc[i][j]));
        }
    }

    // epilogue: unpack, bias, store, per-channel sum/sumsq
    float bj[8], bsum[8], bsq[8];
    #pragma unroll
    for (int j = 0; j < 8; j++) { bj[j] = bias[c0 + tx*8 + j]; bsum[j] = 0.f; bsq[j] = 0.f; }
    #pragma unroll
    for (int i = 0; i < 8; i++) {
        int row = n0 + ty*8 + i;
        float v[8];
        #pragma unroll
        for (int j = 0; j < 4; j++) {
            float lo, hi;
            asm("mov.b64 {%0, %1}, %2;" : "=f"(lo), "=f"(hi) : "l"(acc[i][j]));
            v[2*j]   = lo + bj[2*j];
            v[2*j+1] = hi + bj[2*j+1];
        }
        #pragma unroll
        for (int j = 0; j < 8; j++) {
            bsum[j] += v[j];
            bsq[j]  = fmaf(v[j], v[j], bsq[j]);
        }
        float4* dst = (float4*)(Z + (size_t)row * Cout + c0 + tx*8);
        dst[0] = make_float4(v[0], v[1], v[2], v[3]);
        dst[1] = make_float4(v[4], v[5], v[6], v[7]);
    }
    #pragma unroll
    for (int j = 0; j < 8; j++) {
        atomicAdd(&sSum[tx*8+j], bsum[j]);
        atomicAdd(&sSq[tx*8+j],  bsq[j]);
    }
    __syncthreads();
    if (tid < 128) {
        atomicAdd(&stats[c0 + tid],        (double)sSum[tid]);
        atomicAdd(&stats[Cout + c0 + tid], (double)sSq[tid]);
    }
}

// ---------------- fold BN into a*z + b (double precision stats) ----------------
__global__ void k_bnprep(const double* __restrict__ st, const float* __restrict__ g,
                         const float* __restrict__ be, float* __restrict__ ab, int C) {
    int c = threadIdx.x;
    if (c < C) {
        double mu  = st[c] * (1.0/NTOT);
        double var = st[C + c] * (1.0/NTOT) - mu*mu;
        float a = g[c] * (float)(1.0 / sqrt(var + 1e-5));
        ab[c]     = a;
        ab[C + c] = fmaf((float)(-mu), a, be[c]);
    }
}

// ---------------- final BN3+ReLU + transpose to [B,128,NY] ----------------
__global__ void k_out(float* __restrict__ out) {
    __shared__ float t[32][33];
    int n0 = blockIdx.x * 32;
    int c0 = blockIdx.y * 32;
    int tx = threadIdx.x, ty = threadIdx.y;    // (32, 8)
    float a  = g_ab3[c0 + tx];
    float sh = g_ab3[C3 + c0 + tx];
    #pragma unroll
    for (int i = 0; i < 32; i += 8) {
        float z = g_Z3[(size_t)(n0 + ty + i) * C3 + c0 + tx];
        t[ty + i][tx] = fmaxf(fmaf(a, z, sh), 0.f);
    }
    __syncthreads();
    int b  = n0 >> 14;
    int nl = n0 & (NY - 1);
    #pragma unroll
    for (int i = 0; i < 32; i += 8) {
        int c = c0 + ty + i;
        out[((size_t)b * C3 + c) * NY + nl + tx] = t[tx][ty + i];
    }
}

// ---------------- launch ----------------
extern "C" void kernel_launch(void* const* d_in, const int* in_sizes, int n_in,
                              void* d_out, int out_size) {
    (void)in_sizes; (void)n_in; (void)out_size;
    const float* y_points = (const float*)d_in[0];
    const float* y_feats  = (const float*)d_in[1];
    const float* x_points = (const float*)d_in[2];
    const float* x_feats  = (const float*)d_in[3];
    const float* W1  = (const float*)d_in[4];
    const float* b1  = (const float*)d_in[5];
    const float* g1  = (const float*)d_in[6];
    const float* be1 = (const float*)d_in[7];
    const float* W2  = (const float*)d_in[8];
    const float* b2  = (const float*)d_in[9];
    const float* g2  = (const float*)d_in[10];
    const float* be2 = (const float*)d_in[11];
    const float* W3  = (const float*)d_in[12];
    const float* b3  = (const float*)d_in[13];
    const float* g3  = (const float*)d_in[14];
    const float* be3 = (const float*)d_in[15];
    float* out = (float*)d_out;

    float *pF0, *pZ1, *pZ2, *pZ3, *pAb1, *pAb2, *pAb3;
    double *pSt1, *pSt2, *pSt3;
    cudaGetSymbolAddress((void**)&pF0,  g_F0);
    cudaGetSymbolAddress((void**)&pZ1,  g_Z1);
    cudaGetSymbolAddress((void**)&pZ2,  g_Z2);
    cudaGetSymbolAddress((void**)&pZ3,  g_Z3);
    cudaGetSymbolAddress((void**)&pSt1, g_stats1);
    cudaGetSymbolAddress((void**)&pSt2, g_stats2);
    cudaGetSymbolAddress((void**)&pSt3, g_stats3);
    cudaGetSymbolAddress((void**)&pAb1, g_ab1);
    cudaGetSymbolAddress((void**)&pAb2, g_ab2);
    cudaGetSymbolAddress((void**)&pAb3, g_ab3);

    k_pack<<<64, 256>>>(x_points);
    k_knn<<<dim3(NY/256, BB), 256>>>(y_points);
    k_gather<<<NTOT, 128>>>(y_feats, x_feats);

    k_gemm<DIM, C1, false><<<dim3(NTOT/128, C1/128), 256>>>(pF0, W1, b1, nullptr, pZ1, pSt1);
    k_bnprep<<<1, C1>>>(pSt1, g1, be1, pAb1, C1);

    k_gemm<C1, C2, true><<<dim3(NTOT/128, C2/128), 256>>>(pZ1, W2, b2, pAb1, pZ2, pSt2);
    k_bnprep<<<1, C2>>>(pSt2, g2, be2, pAb2, C2);

    k_gemm<C2, C3, true><<<dim3(NTOT/128, C3/128), 256>>>(pZ2, W3, b3, pAb2, pZ3, pSt3);
    k_bnprep<<<1, C3>>>(pSt3, g3, be3, pAb3, C3);

    k_out<<<dim3(NTOT/32, C3/32), dim3(32, 8)>>>(out);
}

// round 5
// speedup vs baseline: 1.0173x; 1.0173x over previous
#include <cuda_runtime.h>
#include <cuda_bf16.h>
#include <math.h>
#include <stdint.h>

#define BB   4
#define NY   16384
#define NX   4096
#define CY   128
#define CX   256
#define DIM  384
#define C1   512
#define C2   256
#define C3   128
#define NTOT (BB*NY)   // 65536

// ---------------- scratch (static device allocations) ----------------
__device__ float4 g_xpack[BB*NX];
__device__ int    g_nbi[NTOT*3];
__device__ float  g_nbw[NTOT*3];
__device__ float  g_F0[(size_t)NTOT*DIM];
__device__ float  g_Z1[(size_t)NTOT*C1];
__device__ float  g_Z2[(size_t)NTOT*C2];
__device__ float  g_Z3[(size_t)NTOT*C3];
__device__ double g_stats1[2*C1];
__device__ double g_stats2[2*C2];
__device__ double g_stats3[2*C3];
__device__ float  g_ab1[2*C1];
__device__ float  g_ab2[2*C2];
__device__ float  g_ab3[2*C3];

__device__ __forceinline__ uint32_t smem_u32(const void* p) {
    uint32_t a;
    asm("{ .reg .u64 t; cvta.to.shared.u64 t, %1; cvt.u32.u64 %0, t; }" : "=r"(a) : "l"(p));
    return a;
}
// pack two fp32 -> bf16x2 {lo: a, hi: b}
__device__ __forceinline__ uint32_t cvt_bf2(float a, float b) {
    uint32_t r;
    asm("cvt.rn.bf16x2.f32 %0, %1, %2;" : "=r"(r) : "f"(b), "f"(a));
    return r;
}

// ---------------- pack x points + zero stats ----------------
__global__ void k_pack(const float* __restrict__ xp) {
    int i = blockIdx.x * 256 + threadIdx.x;
    if (i < BB*NX) {
        float x = xp[i*3+0], y = xp[i*3+1], z = xp[i*3+2];
        float sx = __fadd_rn(__fadd_rn(__fmul_rn(x,x), __fmul_rn(y,y)), __fmul_rn(z,z));
        g_xpack[i] = make_float4(x, y, z, sx);
    }
    if (i < 2*C1) g_stats1[i] = 0.0;
    else if (i < 2*C1 + 2*C2) g_stats2[i - 2*C1] = 0.0;
    else if (i < 2*C1 + 2*C2 + 2*C3) g_stats3[i - 2*C1 - 2*C2] = 0.0;
}

// ---------------- 3-NN search (exact reference arithmetic order) ----------------
__global__ void k_knn(const float* __restrict__ yp) {
    __shared__ float4 sx[2048];
    int b = blockIdx.y;
    int n = b * NY + blockIdx.x * blockDim.x + threadIdx.x;
    float yx = yp[n*3+0], yy = yp[n*3+1], yz = yp[n*3+2];
    float sy = __fadd_rn(__fadd_rn(__fmul_rn(yx,yx), __fmul_rn(yy,yy)), __fmul_rn(yz,yz));
    float k0 = 1e30f, k1 = 1e30f, k2 = 1e30f;
    int   i0 = 0, i1 = 0, i2 = 0;

    for (int base = 0; base < NX; base += 2048) {
        __syncthreads();
        for (int i = threadIdx.x; i < 2048; i += blockDim.x)
            sx[i] = g_xpack[b*NX + base + i];
        __syncthreads();
        #pragma unroll 4
        for (int j = 0; j < 2048; j++) {
            float4 p = sx[j];
            float dot = __fmaf_rn(yz, p.z, __fmaf_rn(yy, p.y, __fmul_rn(yx, p.x)));
            float d = __fadd_rn(__fadd_rn(sy, p.w), -__fmul_rn(2.0f, dot));
            if (d < k2) {
                int jj = base + j;
                if (d < k1) {
                    k2 = k1; i2 = i1;
                    if (d < k0) { k1 = k0; i1 = i0; k0 = d; i0 = jj; }
                    else        { k1 = d; i1 = jj; }
                } else { k2 = d; i2 = jj; }
            }
        }
    }
    float w0 = __fdiv_rn(1.0f, __fadd_rn(k0, 1e-8f));
    float w1 = __fdiv_rn(1.0f, __fadd_rn(k1, 1e-8f));
    float w2 = __fdiv_rn(1.0f, __fadd_rn(k2, 1e-8f));
    float sw = __fadd_rn(__fadd_rn(w0, w1), w2);
    g_nbi[n*3+0] = i0; g_nbi[n*3+1] = i1; g_nbi[n*3+2] = i2;
    g_nbw[n*3+0] = __fdiv_rn(w0, sw);
    g_nbw[n*3+1] = __fdiv_rn(w1, sw);
    g_nbw[n*3+2] = __fdiv_rn(w2, sw);
}

// ---------------- gather + interpolate + concat -> F0 [N,384] ----------------
__global__ void k_gather(const float* __restrict__ yf, const float* __restrict__ xf) {
    int n = blockIdx.x;
    int t = threadIdx.x;
    int b = n >> 14;
    float* o = g_F0 + (size_t)n * DIM;
    o[t] = yf[(size_t)n * CY + t];
    int i0 = g_nbi[n*3+0], i1 = g_nbi[n*3+1], i2 = g_nbi[n*3+2];
    float w0 = g_nbw[n*3+0], w1 = g_nbw[n*3+1], w2 = g_nbw[n*3+2];
    const float* r0 = xf + ((size_t)(b*NX + i0)) * CX;
    const float* r1 = xf + ((size_t)(b*NX + i1)) * CX;
    const float* r2 = xf + ((size_t)(b*NX + i2)) * CX;
    o[CY + t] = __fadd_rn(__fadd_rn(__fmul_rn(r0[t], w0), __fmul_rn(r1[t], w1)),
                          __fmul_rn(r2[t], w2));
    o[CY + 128 + t] = __fadd_rn(__fadd_rn(__fmul_rn(r0[128+t], w0), __fmul_rn(r1[128+t], w1)),
                                __fmul_rn(r2[128+t], w2));
}

// ---------------- mma.sync GEMM: Z = act(A)·W^T + bias; + BN stats ----------------
// fp32 split into bf16 hi/lo; D = Ah·Wh + Ah·Wl + Al·Wh (fp32 accum).
// CTA tile 128x128, 8 warps (4 m x 2 n), warp tile 32x64. K-chunk = 32.
#define SMS 40   // smem row stride in bf16 elems (80B: conflict-free ldmatrix)

template<int Kd, int Cout, bool ACT>
__global__ void __launch_bounds__(256)
k_gemm(const float* __restrict__ A, const float* __restrict__ W,
       const float* __restrict__ bias, const float* __restrict__ ab,
       float* __restrict__ Z, double* __restrict__ stats)
{
    __shared__ __align__(16) unsigned short sAh[128*SMS], sAl[128*SMS];
    __shared__ __align__(16) unsigned short sWh[128*SMS], sWl[128*SMS];
    __shared__ float sSum[128], sSq[128];

    int tid = threadIdx.x;
    int L = tid & 31, w = tid >> 5;
    int wm = w & 3, wn = w >> 2;              // warp grid 4 x 2
    int g = L >> 2, q = L & 3;
    int n0 = blockIdx.x * 128;
    int c0 = blockIdx.y * 128;
    if (tid < 128) { sSum[tid] = 0.f; sSq[tid] = 0.f; }

    float acc[2][8][4];
    #pragma unroll
    for (int mt = 0; mt < 2; mt++)
        #pragma unroll
        for (int nt = 0; nt < 8; nt++)
            #pragma unroll
            for (int k = 0; k < 4; k++) acc[mt][nt][k] = 0.f;

    uint32_t uAh = smem_u32(sAh), uAl = smem_u32(sAl);
    uint32_t uWh = smem_u32(sWh), uWl = smem_u32(sWl);

    int lrow = tid >> 1;            // loader: tile row 0..127
    int lhalf = tid & 1;            // k half: 0 or 16
    int lk = lhalf * 16;

    int fr = L & 15;                // ldmatrix row within 16
    int fk8 = (L >> 4) * 8;         // ldmatrix k-half offset

    for (int kt = 0; kt < Kd; kt += 32) {
        __syncthreads();
        {   // ---- A chunk -> sAh/sAl (fused BN+ReLU) ----
            const float* src = A + (size_t)(n0 + lrow) * Kd + kt + lk;
            float v[16];
            #pragma unroll
            for (int j = 0; j < 4; j++) *(float4*)&v[4*j] = __ldg((const float4*)(src + 4*j));
            if (ACT) {
                #pragma unroll
                for (int j = 0; j < 16; j++) {
                    float aa = __ldg(ab + kt + lk + j);
                    float ss = __ldg(ab + Kd + kt + lk + j);
                    v[j] = fmaxf(fmaf(aa, v[j], ss), 0.f);
                }
            }
            uint32_t hp[8], lp[8];
            #pragma unroll
            for (int j = 0; j < 8; j++) {
                uint32_t h = cvt_bf2(v[2*j], v[2*j+1]);
                float h0 = __uint_as_float(h << 16);
                float h1 = __uint_as_float(h & 0xFFFF0000u);
                hp[j] = h;
                lp[j] = cvt_bf2(v[2*j] - h0, v[2*j+1] - h1);
            }
            uint4* dh = (uint4*)&sAh[lrow*SMS + lk];
            uint4* dl = (uint4*)&sAl[lrow*SMS + lk];
            dh[0] = make_uint4(hp[0],hp[1],hp[2],hp[3]);
            dh[1] = make_uint4(hp[4],hp[5],hp[6],hp[7]);
            dl[0] = make_uint4(lp[0],lp[1],lp[2],lp[3]);
            dl[1] = make_uint4(lp[4],lp[5],lp[6],lp[7]);
        }
        {   // ---- W chunk -> sWh/sWl ----
            const float* src = W + (size_t)(c0 + lrow) * Kd + kt + lk;
            float v[16];
            #pragma unroll
            for (int j = 0; j < 4; j++) *(float4*)&v[4*j] = __ldg((const float4*)(src + 4*j));
            uint32_t hp[8], lp[8];
            #pragma unroll
            for (int j = 0; j < 8; j++) {
                uint32_t h = cvt_bf2(v[2*j], v[2*j+1]);
                float h0 = __uint_as_float(h << 16);
                float h1 = __uint_as_float(h & 0xFFFF0000u);
                hp[j] = h;
                lp[j] = cvt_bf2(v[2*j] - h0, v[2*j+1] - h1);
            }
            uint4* dh = (uint4*)&sWh[lrow*SMS + lk];
            uint4* dl = (uint4*)&sWl[lrow*SMS + lk];
            dh[0] = make_uint4(hp[0],hp[1],hp[2],hp[3]);
            dh[1] = make_uint4(hp[4],hp[5],hp[6],hp[7]);
            dl[0] = make_uint4(lp[0],lp[1],lp[2],lp[3]);
            dl[1] = make_uint4(lp[4],lp[5],lp[6],lp[7]);
        }
        __syncthreads();

        #pragma unroll
        for (int pass = 0; pass < 3; pass++) {
            uint32_t ua = (pass == 2) ? uAl : uAh;
            uint32_t uw = (pass == 1) ? uWl : uWh;
            #pragma unroll
            for (int k16 = 0; k16 < 2; k16++) {
                int kc = k16 * 16 + fk8;
                uint32_t af[2][4];
                #pragma unroll
                for (int mt = 0; mt < 2; mt++) {
                    uint32_t addr = ua + (uint32_t)(((wm*32 + mt*16 + fr) * SMS + kc) * 2);
                    asm volatile("ldmatrix.sync.aligned.m8n8.x4.shared.b16 {%0,%1,%2,%3}, [%4];"
                        : "=r"(af[mt][0]), "=r"(af[mt][1]), "=r"(af[mt][2]), "=r"(af[mt][3])
                        : "r"(addr));
                }
                uint32_t bf[4][4];
                #pragma unroll
                for (int np = 0; np < 4; np++) {
                    uint32_t addr = uw + (uint32_t)(((wn*64 + np*16 + fr) * SMS + kc) * 2);
                    asm volatile("ldmatrix.sync.aligned.m8n8.x4.shared.b16 {%0,%1,%2,%3}, [%4];"
                        : "=r"(bf[np][0]), "=r"(bf[np][1]), "=r"(bf[np][2]), "=r"(bf[np][3])
                        : "r"(addr));
                }
                #pragma unroll
                for (int mt = 0; mt < 2; mt++)
                    #pragma unroll
                    for (int nt = 0; nt < 8; nt++) {
                        int np = nt >> 1, s = nt & 1;
                        asm volatile(
                            "mma.sync.aligned.m16n8k16.row.col.f32.bf16.bf16.f32 "
                            "{%0,%1,%2,%3}, {%4,%5,%6,%7}, {%8,%9}, {%0,%1,%2,%3};"
                            : "+f"(acc[mt][nt][0]), "+f"(acc[mt][nt][1]),
                              "+f"(acc[mt][nt][2]), "+f"(acc[mt][nt][3])
                            : "r"(af[mt][0]), "r"(af[mt][1]), "r"(af[mt][2]), "r"(af[mt][3]),
                              "r"(bf[np][s]), "r"(bf[np][s+2]));
                    }
            }
        }
    }

    // ---- epilogue: bias, store, per-channel BN stats ----
    float bj[16];
    #pragma unroll
    for (int j = 0; j < 16; j++)
        bj[j] = __ldg(bias + c0 + wn*64 + (j>>1)*8 + q*2 + (j&1));
    float psum[16], psq[16];
    #pragma unroll
    for (int j = 0; j < 16; j++) { psum[j] = 0.f; psq[j] = 0.f; }

    #pragma unroll
    for (int mt = 0; mt < 2; mt++)
        #pragma unroll
        for (int rp = 0; rp < 2; rp++) {
            int row = n0 + wm*32 + mt*16 + g + rp*8;
            float* zr = Z + (size_t)row * Cout + c0 + wn*64;
            #pragma unroll
            for (int nt = 0; nt < 8; nt++) {
                float v0 = acc[mt][nt][rp*2+0] + bj[nt*2];
                float v1 = acc[mt][nt][rp*2+1] + bj[nt*2+1];
                psum[nt*2]   += v0;  psq[nt*2]   = fmaf(v0, v0, psq[nt*2]);
                psum[nt*2+1] += v1;  psq[nt*2+1] = fmaf(v1, v1, psq[nt*2+1]);
                *(float2*)(zr + nt*8 + q*2) = make_float2(v0, v1);
            }
        }
    #pragma unroll
    for (int j = 0; j < 16; j++) {
        int cl = wn*64 + (j>>1)*8 + q*2 + (j&1);
        atomicAdd(&sSum[cl], psum[j]);
        atomicAdd(&sSq[cl],  psq[j]);
    }
    __syncthreads();
    if (tid < 128) {
        atomicAdd(&stats[c0 + tid],        (double)sSum[tid]);
        atomicAdd(&stats[Cout + c0 + tid], (double)sSq[tid]);
    }
}

// ---------------- fold BN into a*z + b ----------------
__global__ void k_bnprep(const double* __restrict__ st, const float* __restrict__ g,
                         const float* __restrict__ be, float* __restrict__ ab, int C) {
    int c = threadIdx.x;
    if (c < C) {
        double mu  = st[c] * (1.0/NTOT);
        double var = st[C + c] * (1.0/NTOT) - mu*mu;
        float a = g[c] * (float)(1.0 / sqrt(var + 1e-5));
        ab[c]     = a;
        ab[C + c] = fmaf((float)(-mu), a, be[c]);
    }
}

// ---------------- final BN3+ReLU + transpose to [B,128,NY] ----------------
__global__ void k_out(float* __restrict__ out) {
    __shared__ float t[32][33];
    int n0 = blockIdx.x * 32;
    int c0 = blockIdx.y * 32;
    int tx = threadIdx.x, ty = threadIdx.y;
    float a  = g_ab3[c0 + tx];
    float sh = g_ab3[C3 + c0 + tx];
    #pragma unroll
    for (int i = 0; i < 32; i += 8) {
        float z = g_Z3[(size_t)(n0 + ty + i) * C3 + c0 + tx];
        t[ty + i][tx] = fmaxf(fmaf(a, z, sh), 0.f);
    }
    __syncthreads();
    int b  = n0 >> 14;
    int nl = n0 & (NY - 1);
    #pragma unroll
    for (int i = 0; i < 32; i += 8) {
        int c = c0 + ty + i;
        out[((size_t)b * C3 + c) * NY + nl + tx] = t[tx][ty + i];
    }
}

// ---------------- launch ----------------
extern "C" void kernel_launch(void* const* d_in, const int* in_sizes, int n_in,
                              void* d_out, int out_size) {
    (void)in_sizes; (void)n_in; (void)out_size;
    const float* y_points = (const float*)d_in[0];
    const float* y_feats  = (const float*)d_in[1];
    const float* x_points = (const float*)d_in[2];
    const float* x_feats  = (const float*)d_in[3];
    const float* W1  = (const float*)d_in[4];
    const float* b1  = (const float*)d_in[5];
    const float* g1  = (const float*)d_in[6];
    const float* be1 = (const float*)d_in[7];
    const float* W2  = (const float*)d_in[8];
    const float* b2  = (const float*)d_in[9];
    const float* g2  = (const float*)d_in[10];
    const float* be2 = (const float*)d_in[11];
    const float* W3  = (const float*)d_in[12];
    const float* b3  = (const float*)d_in[13];
    const float* g3  = (const float*)d_in[14];
    const float* be3 = (const float*)d_in[15];
    float* out = (float*)d_out;

    float *pF0, *pZ1, *pZ2, *pZ3, *pAb1, *pAb2, *pAb3;
    double *pSt1, *pSt2, *pSt3;
    cudaGetSymbolAddress((void**)&pF0,  g_F0);
    cudaGetSymbolAddress((void**)&pZ1,  g_Z1);
    cudaGetSymbolAddress((void**)&pZ2,  g_Z2);
    cudaGetSymbolAddress((void**)&pZ3,  g_Z3);
    cudaGetSymbolAddress((void**)&pSt1, g_stats1);
    cudaGetSymbolAddress((void**)&pSt2, g_stats2);
    cudaGetSymbolAddress((void**)&pSt3, g_stats3);
    cudaGetSymbolAddress((void**)&pAb1, g_ab1);
    cudaGetSymbolAddress((void**)&pAb2, g_ab2);
    cudaGetSymbolAddress((void**)&pAb3, g_ab3);

    k_pack<<<64, 256>>>(x_points);
    k_knn<<<dim3(NY/256, BB), 256>>>(y_points);
    k_gather<<<NTOT, 128>>>(y_feats, x_feats);

    k_gemm<DIM, C1, false><<<dim3(NTOT/128, C1/128), 256>>>(pF0, W1, b1, nullptr, pZ1, pSt1);
    k_bnprep<<<1, C1>>>(pSt1, g1, be1, pAb1, C1);

    k_gemm<C1, C2, true><<<dim3(NTOT/128, C2/128), 256>>>(pZ1, W2, b2, pAb1, pZ2, pSt2);
    k_bnprep<<<1, C2>>>(pSt2, g2, be2, pAb2, C2);

    k_gemm<C2, C3, true><<<dim3(NTOT/128, C3/128), 256>>>(pZ2, W3, b3, pAb2, pZ3, pSt3);
    k_bnprep<<<1, C3>>>(pSt3, g3, be3, pAb3, C3);

    k_out<<<dim3(NTOT/32, C3/32), dim3(32, 8)>>>(out);
}

// round 6
// speedup vs baseline: 1.5612x; 1.5347x over previous
#include <cuda_runtime.h>
#include <cuda_bf16.h>
#include <math.h>
#include <stdint.h>

#define BB   4
#define NY   16384
#define NX   4096
#define CY   128
#define CX   256
#define DIM  384
#define C1   512
#define C2   256
#define C3   128
#define NTOT (BB*NY)   // 65536

// ---------------- scratch (static device allocations) ----------------
__device__ float4 g_xpack[BB*NX];
__device__ int    g_nbi[NTOT*3];
__device__ float  g_nbw[NTOT*3];
__device__ unsigned short g_Ah[(size_t)NTOT*512];   // activation hi (bf16), reused per layer
__device__ unsigned short g_Al[(size_t)NTOT*512];   // activation lo
__device__ unsigned short g_W1h[C1*DIM], g_W1l[C1*DIM];
__device__ unsigned short g_W2h[C2*C1],  g_W2l[C2*C1];
__device__ unsigned short g_W3h[C3*C2],  g_W3l[C3*C2];
__device__ float  g_Z1[(size_t)NTOT*C1];
__device__ float  g_Z2[(size_t)NTOT*C2];
__device__ float  g_Z3[(size_t)NTOT*C3];
__device__ double g_stats1[2*C1];
__device__ double g_stats2[2*C2];
__device__ double g_stats3[2*C3];
__device__ float  g_ab1[2*C1];
__device__ float  g_ab2[2*C2];
__device__ float  g_ab3[2*C3];

__device__ __forceinline__ uint32_t smem_u32(const void* p) {
    uint32_t a;
    asm("{ .reg .u64 t; cvta.to.shared.u64 t, %1; cvt.u32.u64 %0, t; }" : "=r"(a) : "l"(p));
    return a;
}
__device__ __forceinline__ uint32_t cvt_bf2(float a, float b) {  // {lo:a, hi:b}
    uint32_t r;
    asm("cvt.rn.bf16x2.f32 %0, %1, %2;" : "=r"(r) : "f"(b), "f"(a));
    return r;
}
__device__ __forceinline__ void cpa16(uint32_t dst, const void* src) {
    asm volatile("cp.async.ca.shared.global [%0], [%1], 16;" :: "r"(dst), "l"(src) : "memory");
}
#define CP_COMMIT() asm volatile("cp.async.commit_group;" ::: "memory")
#define CP_WAIT(n)  asm volatile("cp.async.wait_group %0;" :: "n"(n) : "memory")

// ---------------- pack x points + zero stats ----------------
__global__ void k_pack(const float* __restrict__ xp) {
    int i = blockIdx.x * 256 + threadIdx.x;
    if (i < BB*NX) {
        float x = xp[i*3+0], y = xp[i*3+1], z = xp[i*3+2];
        float sx = __fadd_rn(__fadd_rn(__fmul_rn(x,x), __fmul_rn(y,y)), __fmul_rn(z,z));
        g_xpack[i] = make_float4(x, y, z, sx);
    }
    if (i < 2*C1) g_stats1[i] = 0.0;
    else if (i < 2*C1 + 2*C2) g_stats2[i - 2*C1] = 0.0;
    else if (i < 2*C1 + 2*C2 + 2*C3) g_stats3[i - 2*C1 - 2*C2] = 0.0;
}

// ---------------- 3-NN search (exact reference arithmetic order) ----------------
__global__ void k_knn(const float* __restrict__ yp) {
    __shared__ float4 sx[2048];
    int b = blockIdx.y;
    int n = b * NY + blockIdx.x * blockDim.x + threadIdx.x;
    float yx = yp[n*3+0], yy = yp[n*3+1], yz = yp[n*3+2];
    float sy = __fadd_rn(__fadd_rn(__fmul_rn(yx,yx), __fmul_rn(yy,yy)), __fmul_rn(yz,yz));
    float k0 = 1e30f, k1 = 1e30f, k2 = 1e30f;
    int   i0 = 0, i1 = 0, i2 = 0;

    for (int base = 0; base < NX; base += 2048) {
        __syncthreads();
        for (int i = threadIdx.x; i < 2048; i += blockDim.x)
            sx[i] = g_xpack[b*NX + base + i];
        __syncthreads();
        #pragma unroll 4
        for (int j = 0; j < 2048; j++) {
            float4 p = sx[j];
            float dot = __fmaf_rn(yz, p.z, __fmaf_rn(yy, p.y, __fmul_rn(yx, p.x)));
            float d = __fadd_rn(__fadd_rn(sy, p.w), -__fmul_rn(2.0f, dot));
            if (d < k2) {
                int jj = base + j;
                if (d < k1) {
                    k2 = k1; i2 = i1;
                    if (d < k0) { k1 = k0; i1 = i0; k0 = d; i0 = jj; }
                    else        { k1 = d; i1 = jj; }
                } else { k2 = d; i2 = jj; }
            }
        }
    }
    float w0 = __fdiv_rn(1.0f, __fadd_rn(k0, 1e-8f));
    float w1 = __fdiv_rn(1.0f, __fadd_rn(k1, 1e-8f));
    float w2 = __fdiv_rn(1.0f, __fadd_rn(k2, 1e-8f));
    float sw = __fadd_rn(__fadd_rn(w0, w1), w2);
    g_nbi[n*3+0] = i0; g_nbi[n*3+1] = i1; g_nbi[n*3+2] = i2;
    g_nbw[n*3+0] = __fdiv_rn(w0, sw);
    g_nbw[n*3+1] = __fdiv_rn(w1, sw);
    g_nbw[n*3+2] = __fdiv_rn(w2, sw);
}

// ---------------- gather + interpolate + concat -> bf16 hi/lo [N,384] ----------------
__device__ __forceinline__ void split_store(float v, unsigned short* ph, unsigned short* pl) {
    __nv_bfloat16 h = __float2bfloat16_rn(v);
    __nv_bfloat16 l = __float2bfloat16_rn(v - __bfloat162float(h));
    *ph = *reinterpret_cast<unsigned short*>(&h);
    *pl = *reinterpret_cast<unsigned short*>(&l);
}
__global__ void k_gather(const float* __restrict__ yf, const float* __restrict__ xf) {
    int n = blockIdx.x;
    int t = threadIdx.x;
    int b = n >> 14;
    unsigned short* oh = g_Ah + (size_t)n * DIM;
    unsigned short* ol = g_Al + (size_t)n * DIM;
    split_store(yf[(size_t)n * CY + t], oh + t, ol + t);
    int i0 = g_nbi[n*3+0], i1 = g_nbi[n*3+1], i2 = g_nbi[n*3+2];
    float w0 = g_nbw[n*3+0], w1 = g_nbw[n*3+1], w2 = g_nbw[n*3+2];
    const float* r0 = xf + ((size_t)(b*NX + i0)) * CX;
    const float* r1 = xf + ((size_t)(b*NX + i1)) * CX;
    const float* r2 = xf + ((size_t)(b*NX + i2)) * CX;
    float u0 = __fadd_rn(__fadd_rn(__fmul_rn(r0[t], w0), __fmul_rn(r1[t], w1)),
                         __fmul_rn(r2[t], w2));
    float u1 = __fadd_rn(__fadd_rn(__fmul_rn(r0[128+t], w0), __fmul_rn(r1[128+t], w1)),
                         __fmul_rn(r2[128+t], w2));
    split_store(u0, oh + CY + t,       ol + CY + t);
    split_store(u1, oh + CY + 128 + t, ol + CY + 128 + t);
}

// ---------------- weight split fp32 -> bf16 hi/lo ----------------
__global__ void k_wsplit(const float* __restrict__ src, unsigned short* __restrict__ dh,
                         unsigned short* __restrict__ dl, int n) {
    int i = blockIdx.x * 256 + threadIdx.x;
    if (i < n) split_store(src[i], dh + i, dl + i);
}

// ---------------- activation: Z fp32 + BN fold -> bf16 hi/lo ----------------
template<int C>
__global__ void __launch_bounds__(256) k_act(const float* __restrict__ Z,
                                             const float* __restrict__ ab) {
    size_t i4 = ((size_t)blockIdx.x * 256 + threadIdx.x) * 4;
    int col = (int)(i4 & (C - 1));
    float4 z = *(const float4*)(Z + i4);
    float4 aa = __ldg((const float4*)(ab + col));
    float4 ss = __ldg((const float4*)(ab + C + col));
    float v0 = fmaxf(fmaf(aa.x, z.x, ss.x), 0.f);
    float v1 = fmaxf(fmaf(aa.y, z.y, ss.y), 0.f);
    float v2 = fmaxf(fmaf(aa.z, z.z, ss.z), 0.f);
    float v3 = fmaxf(fmaf(aa.w, z.w, ss.w), 0.f);
    uint32_t h01 = cvt_bf2(v0, v1), h23 = cvt_bf2(v2, v3);
    float h0 = __uint_as_float(h01 << 16), h1 = __uint_as_float(h01 & 0xFFFF0000u);
    float h2 = __uint_as_float(h23 << 16), h3 = __uint_as_float(h23 & 0xFFFF0000u);
    uint32_t l01 = cvt_bf2(v0 - h0, v1 - h1), l23 = cvt_bf2(v2 - h2, v3 - h3);
    *(uint2*)(g_Ah + i4) = make_uint2(h01, h23);
    *(uint2*)(g_Al + i4) = make_uint2(l01, l23);
}

// ---------------- mma.sync GEMM with cp.async double buffering ----------------
// D = Ah·Wh + Ah·Wl + Al·Wh (fp32 accum). CTA 128x128, 8 warps (4m x 2n), K-chunk 32.
#define SMS 40                       // smem row stride (bf16 elems), 80B
#define TILE_B (128*SMS*2)           // 10240 B per tile
#define STAGE_B (4*TILE_B)           // Ah,Al,Wh,Wl
#define GEMM_SMEM (2*STAGE_B)        // 81920 B

template<int Kd, int Cout>
__global__ void __launch_bounds__(256)
k_gemm(const unsigned short* __restrict__ Ah, const unsigned short* __restrict__ Al,
       const unsigned short* __restrict__ Wh, const unsigned short* __restrict__ Wl,
       const float* __restrict__ bias, float* __restrict__ Z, double* __restrict__ stats)
{
    extern __shared__ unsigned char dynsm[];
    __shared__ float sSum[128], sSq[128];
    uint32_t ubuf = smem_u32(dynsm);

    int tid = threadIdx.x;
    int L = tid & 31, w = tid >> 5;
    int wm = w & 3, wn = w >> 2;
    int g = L >> 2, q = L & 3;
    int n0 = blockIdx.x * 128;
    int c0 = blockIdx.y * 128;
    if (tid < 128) { sSum[tid] = 0.f; sSq[tid] = 0.f; }

    float acc[2][8][4];
    #pragma unroll
    for (int mt = 0; mt < 2; mt++)
        #pragma unroll
        for (int nt = 0; nt < 8; nt++)
            #pragma unroll
            for (int k = 0; k < 4; k++) acc[mt][nt][k] = 0.f;

    int fr = L & 15, fk8 = (L >> 4) * 8;

    // stage loader: 4 tiles x 128 rows x 64B; 512 slots of 16B x4 tiles
    auto load_stage = [&](int st, int kt) {
        uint32_t sb = ubuf + st * STAGE_B;
        #pragma unroll
        for (int i = 0; i < 2; i++) {
            int slot = tid + i * 256;
            int row = slot >> 2, seg = slot & 3;
            uint32_t doff = (uint32_t)(row * SMS + seg * 8) * 2;
            size_t koff = (size_t)kt + seg * 8;
            cpa16(sb + 0*TILE_B + doff, Ah + (size_t)(n0 + row) * Kd + koff);
            cpa16(sb + 1*TILE_B + doff, Al + (size_t)(n0 + row) * Kd + koff);
            cpa16(sb + 2*TILE_B + doff, Wh + (size_t)(c0 + row) * Kd + koff);
            cpa16(sb + 3*TILE_B + doff, Wl + (size_t)(c0 + row) * Kd + koff);
        }
        CP_COMMIT();
    };

    const int NCH = Kd / 32;
    load_stage(0, 0);

    for (int ch = 0; ch < NCH; ch++) {
        if (ch + 1 < NCH) load_stage((ch + 1) & 1, (ch + 1) * 32);
        if (ch + 1 < NCH) { CP_WAIT(1); } else { CP_WAIT(0); }
        __syncthreads();

        uint32_t sb = ubuf + (ch & 1) * STAGE_B;
        uint32_t uah = sb, ual = sb + TILE_B, uwh = sb + 2*TILE_B, uwl = sb + 3*TILE_B;

        #pragma unroll
        for (int k16 = 0; k16 < 2; k16++) {
            int kc = k16 * 16 + fk8;
            uint32_t ah[2][4], al[2][4];
            #pragma unroll
            for (int mt = 0; mt < 2; mt++) {
                uint32_t ro = (uint32_t)((wm*32 + mt*16 + fr) * SMS + kc) * 2;
                asm volatile("ldmatrix.sync.aligned.m8n8.x4.shared.b16 {%0,%1,%2,%3}, [%4];"
                    : "=r"(ah[mt][0]), "=r"(ah[mt][1]), "=r"(ah[mt][2]), "=r"(ah[mt][3])
                    : "r"(uah + ro));
                asm volatile("ldmatrix.sync.aligned.m8n8.x4.shared.b16 {%0,%1,%2,%3}, [%4];"
                    : "=r"(al[mt][0]), "=r"(al[mt][1]), "=r"(al[mt][2]), "=r"(al[mt][3])
                    : "r"(ual + ro));
            }
            uint32_t wh[4][4], wl[4][4];
            #pragma unroll
            for (int np = 0; np < 4; np++) {
                uint32_t ro = (uint32_t)((wn*64 + np*16 + fr) * SMS + kc) * 2;
                asm volatile("ldmatrix.sync.aligned.m8n8.x4.shared.b16 {%0,%1,%2,%3}, [%4];"
                    : "=r"(wh[np][0]), "=r"(wh[np][1]), "=r"(wh[np][2]), "=r"(wh[np][3])
                    : "r"(uwh + ro));
                asm volatile("ldmatrix.sync.aligned.m8n8.x4.shared.b16 {%0,%1,%2,%3}, [%4];"
                    : "=r"(wl[np][0]), "=r"(wl[np][1]), "=r"(wl[np][2]), "=r"(wl[np][3])
                    : "r"(uwl + ro));
            }
            #pragma unroll
            for (int mt = 0; mt < 2; mt++)
                #pragma unroll
                for (int nt = 0; nt < 8; nt++) {
                    int np = nt >> 1, s = nt & 1;
                    asm volatile(
                        "mma.sync.aligned.m16n8k16.row.col.f32.bf16.bf16.f32 "
                        "{%0,%1,%2,%3}, {%4,%5,%6,%7}, {%8,%9}, {%0,%1,%2,%3};"
                        : "+f"(acc[mt][nt][0]), "+f"(acc[mt][nt][1]),
                          "+f"(acc[mt][nt][2]), "+f"(acc[mt][nt][3])
                        : "r"(ah[mt][0]), "r"(ah[mt][1]), "r"(ah[mt][2]), "r"(ah[mt][3]),
                          "r"(wh[np][s]), "r"(wh[np][s+2]));
                    asm volatile(
                        "mma.sync.aligned.m16n8k16.row.col.f32.bf16.bf16.f32 "
                        "{%0,%1,%2,%3}, {%4,%5,%6,%7}, {%8,%9}, {%0,%1,%2,%3};"
                        : "+f"(acc[mt][nt][0]), "+f"(acc[mt][nt][1]),
                          "+f"(acc[mt][nt][2]), "+f"(acc[mt][nt][3])
                        : "r"(ah[mt][0]), "r"(ah[mt][1]), "r"(ah[mt][2]), "r"(ah[mt][3]),
                          "r"(wl[np][s]), "r"(wl[np][s+2]));
                    asm volatile(
                        "mma.sync.aligned.m16n8k16.row.col.f32.bf16.bf16.f32 "
                        "{%0,%1,%2,%3}, {%4,%5,%6,%7}, {%8,%9}, {%0,%1,%2,%3};"
                        : "+f"(acc[mt][nt][0]), "+f"(acc[mt][nt][1]),
                          "+f"(acc[mt][nt][2]), "+f"(acc[mt][nt][3])
                        : "r"(al[mt][0]), "r"(al[mt][1]), "r"(al[mt][2]), "r"(al[mt][3]),
                          "r"(wh[np][s]), "r"(wh[np][s+2]));
                }
        }
        __syncthreads();
    }

    // ---- epilogue: bias, store, per-channel BN stats ----
    float bj[16];
    #pragma unroll
    for (int j = 0; j < 16; j++)
        bj[j] = __ldg(bias + c0 + wn*64 + (j>>1)*8 + q*2 + (j&1));
    float psum[16], psq[16];
    #pragma unroll
    for (int j = 0; j < 16; j++) { psum[j] = 0.f; psq[j] = 0.f; }

    #pragma unroll
    for (int mt = 0; mt < 2; mt++)
        #pragma unroll
        for (int rp = 0; rp < 2; rp++) {
            int row = n0 + wm*32 + mt*16 + g + rp*8;
            float* zr = Z + (size_t)row * Cout + c0 + wn*64;
            #pragma unroll
            for (int nt = 0; nt < 8; nt++) {
                float v0 = acc[mt][nt][rp*2+0] + bj[nt*2];
                float v1 = acc[mt][nt][rp*2+1] + bj[nt*2+1];
                psum[nt*2]   += v0;  psq[nt*2]   = fmaf(v0, v0, psq[nt*2]);
                psum[nt*2+1] += v1;  psq[nt*2+1] = fmaf(v1, v1, psq[nt*2+1]);
                *(float2*)(zr + nt*8 + q*2) = make_float2(v0, v1);
            }
        }
    #pragma unroll
    for (int j = 0; j < 16; j++) {
        int cl = wn*64 + (j>>1)*8 + q*2 + (j&1);
        atomicAdd(&sSum[cl], psum[j]);
        atomicAdd(&sSq[cl],  psq[j]);
    }
    __syncthreads();
    if (tid < 128) {
        atomicAdd(&stats[c0 + tid],        (double)sSum[tid]);
        atomicAdd(&stats[Cout + c0 + tid], (double)sSq[tid]);
    }
}

// ---------------- fold BN into a*z + b ----------------
__global__ void k_bnprep(const double* __restrict__ st, const float* __restrict__ g,
                         const float* __restrict__ be, float* __restrict__ ab, int C) {
    int c = threadIdx.x;
    if (c < C) {
        double mu  = st[c] * (1.0/NTOT);
        double var = st[C + c] * (1.0/NTOT) - mu*mu;
        float a = g[c] * (float)(1.0 / sqrt(var + 1e-5));
        ab[c]     = a;
        ab[C + c] = fmaf((float)(-mu), a, be[c]);
    }
}

// ---------------- final BN3+ReLU + transpose to [B,128,NY] ----------------
__global__ void k_out(float* __restrict__ out) {
    __shared__ float t[32][33];
    int n0 = blockIdx.x * 32;
    int c0 = blockIdx.y * 32;
    int tx = threadIdx.x, ty = threadIdx.y;
    float a  = g_ab3[c0 + tx];
    float sh = g_ab3[C3 + c0 + tx];
    #pragma unroll
    for (int i = 0; i < 32; i += 8) {
        float z = g_Z3[(size_t)(n0 + ty + i) * C3 + c0 + tx];
        t[ty + i][tx] = fmaxf(fmaf(a, z, sh), 0.f);
    }
    __syncthreads();
    int b  = n0 >> 14;
    int nl = n0 & (NY - 1);
    #pragma unroll
    for (int i = 0; i < 32; i += 8) {
        int c = c0 + ty + i;
        out[((size_t)b * C3 + c) * NY + nl + tx] = t[tx][ty + i];
    }
}

// ---------------- launch ----------------
extern "C" void kernel_launch(void* const* d_in, const int* in_sizes, int n_in,
                              void* d_out, int out_size) {
    (void)in_sizes; (void)n_in; (void)out_size;
    const float* y_points = (const float*)d_in[0];
    const float* y_feats  = (const float*)d_in[1];
    const float* x_points = (const float*)d_in[2];
    const float* x_feats  = (const float*)d_in[3];
    const float* W1  = (const float*)d_in[4];
    const float* b1  = (const float*)d_in[5];
    const float* g1  = (const float*)d_in[6];
    const float* be1 = (const float*)d_in[7];
    const float* W2  = (const float*)d_in[8];
    const float* b2  = (const float*)d_in[9];
    const float* g2  = (const float*)d_in[10];
    const float* be2 = (const float*)d_in[11];
    const float* W3  = (const float*)d_in[12];
    const float* b3  = (const float*)d_in[13];
    const float* g3  = (const float*)d_in[14];
    const float* be3 = (const float*)d_in[15];
    float* out = (float*)d_out;

    float *pZ1, *pZ2, *pZ3, *pAb1, *pAb2, *pAb3;
    double *pSt1, *pSt2, *pSt3;
    unsigned short *pAh, *pAl, *pW1h, *pW1l, *pW2h, *pW2l, *pW3h, *pW3l;
    cudaGetSymbolAddress((void**)&pZ1,  g_Z1);
    cudaGetSymbolAddress((void**)&pZ2,  g_Z2);
    cudaGetSymbolAddress((void**)&pZ3,  g_Z3);
    cudaGetSymbolAddress((void**)&pSt1, g_stats1);
    cudaGetSymbolAddress((void**)&pSt2, g_stats2);
    cudaGetSymbolAddress((void**)&pSt3, g_stats3);
    cudaGetSymbolAddress((void**)&pAb1, g_ab1);
    cudaGetSymbolAddress((void**)&pAb2, g_ab2);
    cudaGetSymbolAddress((void**)&pAb3, g_ab3);
    cudaGetSymbolAddress((void**)&pAh,  g_Ah);
    cudaGetSymbolAddress((void**)&pAl,  g_Al);
    cudaGetSymbolAddress((void**)&pW1h, g_W1h);
    cudaGetSymbolAddress((void**)&pW1l, g_W1l);
    cudaGetSymbolAddress((void**)&pW2h, g_W2h);
    cudaGetSymbolAddress((void**)&pW2l, g_W2l);
    cudaGetSymbolAddress((void**)&pW3h, g_W3h);
    cudaGetSymbolAddress((void**)&pW3l, g_W3l);

    cudaFuncSetAttribute(k_gemm<DIM, C1>, cudaFuncAttributeMaxDynamicSharedMemorySize, GEMM_SMEM);
    cudaFuncSetAttribute(k_gemm<C1, C2>,  cudaFuncAttributeMaxDynamicSharedMemorySize, GEMM_SMEM);
    cudaFuncSetAttribute(k_gemm<C2, C3>,  cudaFuncAttributeMaxDynamicSharedMemorySize, GEMM_SMEM);

    k_pack<<<64, 256>>>(x_points);
    k_knn<<<dim3(NY/256, BB), 256>>>(y_points);
    k_gather<<<NTOT, 128>>>(y_feats, x_feats);
    k_wsplit<<<(C1*DIM + 255)/256, 256>>>(W1, pW1h, pW1l, C1*DIM);
    k_wsplit<<<(C2*C1 + 255)/256, 256>>>(W2, pW2h, pW2l, C2*C1);
    k_wsplit<<<(C3*C2 + 255)/256, 256>>>(W3, pW3h, pW3l, C3*C2);

    k_gemm<DIM, C1><<<dim3(NTOT/128, C1/128), 256, GEMM_SMEM>>>(pAh, pAl, pW1h, pW1l, b1, pZ1, pSt1);
    k_bnprep<<<1, C1>>>(pSt1, g1, be1, pAb1, C1);
    k_act<C1><<<(int)(((size_t)NTOT*C1/4)/256), 256>>>(pZ1, pAb1);

    k_gemm<C1, C2><<<dim3(NTOT/128, C2/128), 256, GEMM_SMEM>>>(pAh, pAl, pW2h, pW2l, b2, pZ2, pSt2);
    k_bnprep<<<1, C2>>>(pSt2, g2, be2, pAb2, C2);
    k_act<C2><<<(int)(((size_t)NTOT*C2/4)/256), 256>>>(pZ2, pAb2);

    k_gemm<C2, C3><<<dim3(NTOT/128, C3/128), 256, GEMM_SMEM>>>(pAh, pAl, pW3h, pW3l, b3, pZ3, pSt3);
    k_bnprep<<<1, C3>>>(pSt3, g3, be3, pAb3, C3);

    k_out<<<dim3(NTOT/32, C3/32), dim3(32, 8)>>>(out);
}